// round 10
// baseline (speedup 1.0000x reference)
#include <cuda_runtime.h>
#include <cuda_bf16.h>
#include <cstdint>
#include <math.h>

#define Tn    2048
#define HIDn  2048
#define Hn    32
#define HKVn  2
#define Dn    64
#define Gn    2
#define HGn   16
#define BLKn  32
#define NSELn 8
#define WINn  256
#define NBn   64
#define OUTDn 2400
#define NPADn 2432          /* 19*128 */
#define K2n   6144          /* 3x K=2048 : [ah,ah,al] x [bh,bl,bh] */
#define KOFF  (Hn*Dn)
#define VOFF  (KOFF + HKVn*Dn)
#define WOFF  (VOFF + HKVn*Dn)
#define NEGf  (-1e30f)
#define SCALEf 0.125f

// ---------------- scratch ----------------
__device__ float g_qkvw[Tn*OUTDn];
__device__ float g_q[Tn*Hn*Dn];
__device__ float g_k[Tn*HKVn*Dn];
__device__ float g_kcmp[NBn*Gn*Dn];
__device__ float g_vcmp[NBn*Gn*Dn];
__device__ float g_pcmp[Tn*Hn*NBn];
__device__ float g_ocmp[Tn*Hn*Dn];
__device__ float g_osel[Tn*Hn*Dn];
__device__ float g_owin[Tn*Hn*Dn];
__device__ int   g_selidx[Tn*Gn*NSELn];
__device__ __align__(16) __nv_bfloat16 g_a2x[(size_t)Tn*K2n];
__device__ __align__(16) __nv_bfloat16 g_a2o[(size_t)Tn*K2n];
__device__ __align__(16) __nv_bfloat16 g_b2q[(size_t)NPADn*K2n];
__device__ __align__(16) __nv_bfloat16 g_b2o[(size_t)HIDn*K2n];

// ---------------- helpers ----------------
__device__ __forceinline__ uint32_t smem_u32(const void* p) {
    uint32_t a;
    asm("{ .reg .u64 t; cvta.to.shared.u64 t, %1; cvt.u32.u64 %0, t; }" : "=r"(a) : "l"(p));
    return a;
}
#define CP_ASYNC16(dst, src) \
    asm volatile("cp.async.cg.shared.global [%0], [%1], 16;" :: "r"(dst), "l"(src) : "memory")
#define CP_COMMIT() asm volatile("cp.async.commit_group;" ::: "memory")
#define CP_WAIT1()  asm volatile("cp.async.wait_group 1;" ::: "memory")
#define CP_WAIT0()  asm volatile("cp.async.wait_group 0;" ::: "memory")

__device__ __forceinline__ void ldsm4(uint32_t &r0, uint32_t &r1, uint32_t &r2, uint32_t &r3,
                                      uint32_t addr) {
    asm volatile("ldmatrix.sync.aligned.m8n8.x4.shared.b16 {%0,%1,%2,%3}, [%4];"
                 : "=r"(r0), "=r"(r1), "=r"(r2), "=r"(r3) : "r"(addr));
}
__device__ __forceinline__ void mma_bf16(float* c, uint32_t a0, uint32_t a1, uint32_t a2,
                                         uint32_t a3, uint32_t b0, uint32_t b1) {
    asm volatile("mma.sync.aligned.m16n8k16.row.col.f32.bf16.bf16.f32 "
                 "{%0,%1,%2,%3}, {%4,%5,%6,%7}, {%8,%9}, {%0,%1,%2,%3};"
                 : "+f"(c[0]), "+f"(c[1]), "+f"(c[2]), "+f"(c[3])
                 : "r"(a0), "r"(a1), "r"(a2), "r"(a3), "r"(b0), "r"(b1));
}

__device__ __forceinline__ float warpMax(float v) {
    #pragma unroll
    for (int o = 16; o > 0; o >>= 1) v = fmaxf(v, __shfl_xor_sync(0xffffffffu, v, o));
    return v;
}
__device__ __forceinline__ float warpSum(float v) {
    #pragma unroll
    for (int o = 16; o > 0; o >>= 1) v += __shfl_xor_sync(0xffffffffu, v, o);
    return v;
}
__device__ __forceinline__ void f32_hl(float v, unsigned short &h, unsigned short &l) {
    __nv_bfloat16 bh = __float2bfloat16(v);
    float r = v - __bfloat162float(bh);
    __nv_bfloat16 bl = __float2bfloat16(r);
    h = __bfloat16_as_ushort(bh);
    l = __bfloat16_as_ushort(bl);
}

// ---------------- mma.sync split-bf16 GEMM body ----------------
// C[M,N] = A2[M,K2] @ B2[N,K2]^T ; 128x128 CTA tile, K-chunk 32, 3-stage dynamic smem.
#define SAst 40                          /* smem row stride in bf16 elems (80 B) */
#define STAGE_BYTES (128*SAst*2)         /* 10240 per operand */
#define STAGE_PAIR  (2*STAGE_BYTES)      /* 20480 */
#define NSTAGE 3
#define GEMM_SMEM (NSTAGE*STAGE_PAIR)    /* 61440 */
__device__ __forceinline__ void gemm_body(const __nv_bfloat16* __restrict__ A2,
                                          const __nv_bfloat16* __restrict__ B2,
                                          float* __restrict__ C,
                                          int Nvalid, int ldc) {
    extern __shared__ __align__(16) unsigned char smem[];
    const uint32_t sbase = smem_u32(smem);
    const int tid = threadIdx.x;
    const int lane = tid & 31;
    const int warp = tid >> 5;
    const int wm = warp >> 2;
    const int wn = warp & 3;
    const int m0 = blockIdx.y * 128;
    const int n0 = blockIdx.x * 128;

    const int lrow = tid >> 2;
    const int lk   = (tid & 3) * 8;
    const __nv_bfloat16* aG = A2 + (size_t)(m0 + lrow) * K2n + lk;
    const __nv_bfloat16* bG = B2 + (size_t)(n0 + lrow) * K2n + lk;
    const uint32_t wOff0 = (uint32_t)(lrow * SAst + lk) * 2;
    const uint32_t wOff1 = (uint32_t)((lrow + 64) * SAst + lk) * 2;

    float acc[4][4][4];
    #pragma unroll
    for (int i = 0; i < 4; i++)
        #pragma unroll
        for (int j = 0; j < 4; j++)
            #pragma unroll
            for (int r = 0; r < 4; r++) acc[i][j][r] = 0.f;

    const int NK = K2n / 32;   // 192

    const uint32_t aRow = (uint32_t)(wm * 64 + (lane & 15));
    const uint32_t aColSel = (uint32_t)((lane >> 4) * 8);
    const int ro = lane >> 3;
    const uint32_t bRow = (uint32_t)(wn * 32 + ((ro & 2) ? 8 : 0) + (lane & 7));
    const uint32_t bColSel = (uint32_t)((ro & 1) ? 8 : 0);

    #pragma unroll
    for (int s = 0; s < 2; s++) {
        uint32_t sA = sbase + (uint32_t)s * STAGE_PAIR;
        uint32_t sB = sA + STAGE_BYTES;
        CP_ASYNC16(sA + wOff0, aG + (size_t)s * 32);
        CP_ASYNC16(sA + wOff1, aG + (size_t)64 * K2n + (size_t)s * 32);
        CP_ASYNC16(sB + wOff0, bG + (size_t)s * 32);
        CP_ASYNC16(sB + wOff1, bG + (size_t)64 * K2n + (size_t)s * 32);
        CP_COMMIT();
    }

    for (int kc = 0; kc < NK; kc++) {
        if (kc + 2 < NK) CP_WAIT1(); else CP_WAIT0();
        __syncthreads();

        if (kc + 2 < NK) {
            uint32_t st = (uint32_t)((kc + 2) % 3) * STAGE_PAIR;
            uint32_t sA = sbase + st;
            uint32_t sB = sA + STAGE_BYTES;
            CP_ASYNC16(sA + wOff0, aG + (size_t)(kc + 2) * 32);
            CP_ASYNC16(sA + wOff1, aG + (size_t)64 * K2n + (size_t)(kc + 2) * 32);
            CP_ASYNC16(sB + wOff0, bG + (size_t)(kc + 2) * 32);
            CP_ASYNC16(sB + wOff1, bG + (size_t)64 * K2n + (size_t)(kc + 2) * 32);
            CP_COMMIT();
        }

        uint32_t st = (uint32_t)(kc % 3) * STAGE_PAIR;
        uint32_t sA = sbase + st;
        uint32_t sB = sA + STAGE_BYTES;

        #pragma unroll
        for (int s = 0; s < 2; s++) {
            uint32_t af[4][4];
            #pragma unroll
            for (int i = 0; i < 4; i++) {
                uint32_t addr = sA + ((aRow + i * 16) * SAst + s * 16 + aColSel) * 2;
                ldsm4(af[i][0], af[i][1], af[i][2], af[i][3], addr);
            }
            uint32_t bf[4][2];
            #pragma unroll
            for (int j2 = 0; j2 < 2; j2++) {
                uint32_t addr = sB + ((bRow + j2 * 16) * SAst + s * 16 + bColSel) * 2;
                uint32_t r0, r1, r2, r3;
                ldsm4(r0, r1, r2, r3, addr);
                bf[2*j2][0] = r0; bf[2*j2][1] = r1;
                bf[2*j2+1][0] = r2; bf[2*j2+1][1] = r3;
            }
            #pragma unroll
            for (int i = 0; i < 4; i++)
                #pragma unroll
                for (int j = 0; j < 4; j++)
                    mma_bf16(acc[i][j], af[i][0], af[i][1], af[i][2], af[i][3],
                             bf[j][0], bf[j][1]);
        }
    }

    const int rbase = m0 + wm * 64 + (lane >> 2);
    const int cbase = n0 + wn * 32 + (lane & 3) * 2;
    #pragma unroll
    for (int i = 0; i < 4; i++) {
        #pragma unroll
        for (int j = 0; j < 4; j++) {
            int rr = rbase + i * 16;
            int cc = cbase + j * 8;
            if (cc < Nvalid) {
                float* p0 = C + (size_t)rr * ldc + cc;
                p0[0] = acc[i][j][0];
                if (cc + 1 < Nvalid) p0[1] = acc[i][j][1];
                float* p1 = C + (size_t)(rr + 8) * ldc + cc;
                p1[0] = acc[i][j][2];
                if (cc + 1 < Nvalid) p1[1] = acc[i][j][3];
            }
        }
    }
}

__global__ __launch_bounds__(256) void gemm_mma_qkvw() {
    gemm_body(g_a2x, g_b2q, g_qkvw, OUTDn, OUTDn);
}
__global__ __launch_bounds__(256) void gemm_mma_out(float* __restrict__ C) {
    gemm_body(g_a2o, g_b2o, C, HIDn, HIDn);
}

// ---------------- conversions (3-term split: A=[h,h,l], B=[h,l,h]) ----------------
__global__ void conv_x_kernel(const float* __restrict__ x) {
    int idx = blockIdx.x * blockDim.x + threadIdx.x;
    if (idx >= Tn * HIDn) return;
    unsigned short h, l;
    f32_hl(x[idx], h, l);
    unsigned short* p = (unsigned short*)g_a2x + (size_t)idx * 3;
    p[0] = h; p[1] = h; p[2] = l;
}
__device__ __forceinline__ void tr_body(const float* __restrict__ W,
                                        __nv_bfloat16* __restrict__ B2,
                                        int Ncols, int Npad) {
    __shared__ float tile[32][33];
    int n = blockIdx.x * 32 + threadIdx.x;
    int k = blockIdx.y * 32 + threadIdx.y;
    tile[threadIdx.y][threadIdx.x] = (n < Ncols) ? W[(size_t)k * Ncols + n] : 0.f;
    __syncthreads();
    int nn = blockIdx.x * 32 + threadIdx.y;
    int kk = blockIdx.y * 32 + threadIdx.x;
    if (nn < Npad) {
        unsigned short h, l;
        f32_hl(tile[threadIdx.x][threadIdx.y], h, l);
        unsigned short* p = (unsigned short*)B2 + (size_t)nn * K2n + (size_t)kk * 3;
        p[0] = h; p[1] = l; p[2] = h;
    }
}
__global__ void tr_q_kernel(const float* __restrict__ W) { tr_body(W, g_b2q, OUTDn, NPADn); }
__global__ void tr_o_kernel(const float* __restrict__ W) { tr_body(W, g_b2o, HIDn, HIDn); }

// ---------------- RoPE ----------------
__global__ void rope_kernel(const float* __restrict__ cosp, const float* __restrict__ sinp) {
    int idx = blockIdx.x * blockDim.x + threadIdx.x;
    const int total = Tn * (Hn + HKVn) * Dn;
    if (idx >= total) return;
    const int d = idx & 63;
    int rest = idx >> 6;
    const int h = rest % (Hn + HKVn);
    const int t = rest / (Hn + HKVn);
    const float c = cosp[t * Dn + d];
    const float s = sinp[t * Dn + d];
    if (h < Hn) {
        const float* row = g_qkvw + (size_t)t * OUTDn + h * Dn;
        float x = row[d];
        float rot = (d < 32) ? -row[d + 32] : row[d - 32];
        g_q[((size_t)t * Hn + h) * Dn + d] = x * c + rot * s;
    } else {
        const int g = h - Hn;
        const float* row = g_qkvw + (size_t)t * OUTDn + KOFF + g * Dn;
        float x = row[d];
        float rot = (d < 32) ? -row[d + 32] : row[d - 32];
        g_k[((size_t)t * HKVn + g) * Dn + d] = x * c + rot * s;
    }
}

// ---------------- mean-pool ----------------
__global__ void pool_kernel() {
    int idx = blockIdx.x * blockDim.x + threadIdx.x;
    if (idx >= NBn * Gn * Dn) return;
    const int d = idx & 63;
    int rest = idx >> 6;
    const int g = rest % Gn;
    const int n = rest / Gn;
    float sk = 0.f, sv = 0.f;
    #pragma unroll 4
    for (int b = 0; b < BLKn; b++) {
        const int t = n * BLKn + b;
        sk += g_k[((size_t)t * HKVn + g) * Dn + d];
        sv += g_qkvw[(size_t)t * OUTDn + VOFF + g * Dn + d];
    }
    g_kcmp[idx] = sk * (1.f / BLKn);
    g_vcmp[idx] = sv * (1.f / BLKn);
}

// ---------------- compressed attention: CTA per (t,g), warp per head ----------------
__global__ __launch_bounds__(512) void cmp2_kernel() {
    const int t = blockIdx.x, g = blockIdx.y;
    const int tid = threadIdx.x, w = tid >> 5, lane = tid & 31;
    __shared__ float kc[NBn][65], vc[NBn][65], qs[HGn][Dn], ps[HGn][NBn];

    for (int i = tid; i < NBn * Dn; i += 512) {
        int n = i >> 6, d = i & 63;
        kc[n][d] = g_kcmp[((size_t)n * Gn + g) * Dn + d];
        vc[n][d] = g_vcmp[((size_t)n * Gn + g) * Dn + d];
    }
    for (int i = tid; i < HGn * Dn; i += 512) {
        int hg = i >> 6, d = i & 63;
        qs[hg][d] = g_q[((size_t)t * Hn + g * HGn + hg) * Dn + d];
    }
    __syncthreads();

    const int nvis = (t + 1) >> 5;
    float sc[2];
    #pragma unroll
    for (int ii = 0; ii < 2; ii++) {
        const int n = lane + ii * 32;
        float s = NEGf;
        if (n < nvis) {
            float acc = 0.f;
            #pragma unroll
            for (int d = 0; d < Dn; d++) acc = fmaf(qs[w][d], kc[n][d], acc);
            s = acc * SCALEf;
        }
        sc[ii] = s;
    }
    float p0 = 0.f, p1 = 0.f;
    if (nvis > 0) {
        float m = warpMax(fmaxf(sc[0], sc[1]));
        float e0 = expf(sc[0] - m), e1 = expf(sc[1] - m);
        float inv = 1.f / warpSum(e0 + e1);
        p0 = e0 * inv; p1 = e1 * inv;
    }
    ps[w][lane] = p0; ps[w][lane + 32] = p1;
    float* pout = g_pcmp + ((size_t)t * Hn + g * HGn + w) * NBn;
    pout[lane] = p0; pout[lane + 32] = p1;
    __syncwarp();

    float a0 = 0.f, a1 = 0.f;
    for (int n = 0; n < nvis; n++) {
        const float p = ps[w][n];
        a0 = fmaf(p, vc[n][lane], a0);
        a1 = fmaf(p, vc[n][lane + 32], a1);
    }
    float* orow = g_ocmp + ((size_t)t * Hn + g * HGn + w) * Dn;
    orow[lane] = a0; orow[lane + 32] = a1;
}

// ---------------- top-8 ----------------
__global__ void topk_kernel() {
    int idx = blockIdx.x * blockDim.x + threadIdx.x;
    if (idx >= Tn * Gn) return;
    const int g = idx % Gn, t = idx / Gn, tb = t >> 5;
    float imp[NBn];
    for (int n = 0; n < NBn; n++) {
        if (n > tb) { imp[n] = NEGf; continue; }
        float s = 0.f;
        #pragma unroll
        for (int hg = 0; hg < HGn; hg++)
            s += g_pcmp[((size_t)t * Hn + g * HGn + hg) * NBn + n];
        if (n == 0)  s += 1e4f;
        if (n == tb) s += 1e4f;
        imp[n] = s;
    }
    int* sel = g_selidx + ((size_t)t * Gn + g) * NSELn;
    for (int i = 0; i < NSELn; i++) {
        int best = 0; float bv = imp[0];
        for (int n = 1; n < NBn; n++)
            if (imp[n] > bv) { bv = imp[n]; best = n; }
        sel[i] = best;
        imp[best] = -2e30f;
    }
}

// ---------------- selection attention: CTA per (t,g) ----------------
__global__ __launch_bounds__(512) void sel2_kernel() {
    const int t = blockIdx.x, g = blockIdx.y;
    const int tid = threadIdx.x, w = tid >> 5, lane = tid & 31;
    __shared__ float kb[BLKn][65], qs[HGn][Dn], ps[HGn][NSELn * BLKn];
    __shared__ int sel[NSELn];

    for (int i = tid; i < HGn * Dn; i += 512) {
        int hg = i >> 6, d = i & 63;
        qs[hg][d] = g_q[((size_t)t * Hn + g * HGn + hg) * Dn + d];
    }
    if (tid < NSELn) sel[tid] = g_selidx[((size_t)t * Gn + g) * NSELn + tid];
    __syncthreads();

    float sc[NSELn];
    for (int i = 0; i < NSELn; i++) {
        const int base = sel[i] * BLKn;
        for (int j = tid; j < BLKn * Dn; j += 512) {
            int b = j >> 6, d = j & 63;
            kb[b][d] = g_k[((size_t)(base + b) * HKVn + g) * Dn + d];
        }
        __syncthreads();
        const int pos = base + lane;
        float s = NEGf;
        if (pos <= t) {
            float acc = 0.f;
            #pragma unroll
            for (int d = 0; d < Dn; d++) acc = fmaf(qs[w][d], kb[lane][d], acc);
            s = acc * SCALEf;
        }
        sc[i] = s;
        __syncthreads();
    }
    float lm = sc[0];
    #pragma unroll
    for (int i = 1; i < NSELn; i++) lm = fmaxf(lm, sc[i]);
    float m = warpMax(lm);
    float lsum = 0.f, ev[NSELn];
    #pragma unroll
    for (int i = 0; i < NSELn; i++) { ev[i] = expf(sc[i] - m); lsum += ev[i]; }
    float inv = 1.f / warpSum(lsum);
    #pragma unroll
    for (int i = 0; i < NSELn; i++) ps[w][i * 32 + lane] = ev[i] * inv;
    __syncwarp();

    float a0 = 0.f, a1 = 0.f;
    for (int i = 0; i < NSELn; i++) {
        const int base = sel[i] * BLKn;
        for (int j = tid; j < BLKn * Dn; j += 512) {
            int b = j >> 6, d = j & 63;
            kb[b][d] = g_qkvw[(size_t)(base + b) * OUTDn + VOFF + g * Dn + d];
        }
        __syncthreads();
        if (base <= t) {
            for (int b = 0; b < BLKn; b++) {
                const float p = ps[w][i * 32 + b];
                a0 = fmaf(p, kb[b][lane], a0);
                a1 = fmaf(p, kb[b][lane + 32], a1);
            }
        }
        __syncthreads();
    }
    float* orow = g_osel + ((size_t)t * Hn + g * HGn + w) * Dn;
    orow[lane] = a0; orow[lane + 32] = a1;
}

// ---------------- sliding window v3: CTA per (8-t block, g), online softmax ----------------
#define TBw 8
#define WIN3_SMEM ((HGn*TBw*Dn + 32*65 + 32*64) * 4)   /* 49280 bytes */
__global__ __launch_bounds__(512) void win3_kernel() {
    extern __shared__ float dsm[];
    float* qs = dsm;                        // [HGn][TBw][Dn]
    float* kb = dsm + HGn * TBw * Dn;       // [32][65]
    float* vb = kb + 32 * 65;               // [32][64]
    const int t0 = blockIdx.x * TBw, g = blockIdx.y;
    const int tid = threadIdx.x, w = tid >> 5, lane = tid & 31;

    for (int i = tid; i < HGn * TBw * Dn; i += 512) {
        int d = i & 63;
        int rest = i >> 6;
        int tl = rest & (TBw - 1);
        int hg = rest / TBw;
        qs[(hg * TBw + tl) * Dn + d] = g_q[((size_t)(t0 + tl) * Hn + g * HGn + hg) * Dn + d];
    }

    float m[TBw], l[TBw], o0[TBw], o1[TBw];
    #pragma unroll
    for (int tl = 0; tl < TBw; tl++) { m[tl] = NEGf; l[tl] = 0.f; o0[tl] = 0.f; o1[tl] = 0.f; }

    const int start = t0 - (WINn - 1);
    for (int c = 0; c < 9; c++) {
        __syncthreads();
        for (int i = tid; i < 32 * Dn; i += 512) {
            int b = i >> 6, d = i & 63;
            int pos = start + c * 32 + b;
            int rp = pos < 0 ? 0 : (pos >= Tn ? Tn - 1 : pos);
            kb[b * 65 + d] = g_k[((size_t)rp * HKVn + g) * Dn + d];
            vb[b * 64 + d] = g_qkvw[(size_t)rp * OUTDn + VOFF + g * Dn + d];
        }
        __syncthreads();
        const int pos = start + c * 32 + lane;
        #pragma unroll
        for (int tl = 0; tl < TBw; tl++) {
            const int tg = t0 + tl;
            float s = 0.f;
            const float* qrow = qs + (w * TBw + tl) * Dn;
            #pragma unroll
            for (int d = 0; d < Dn; d++) s = fmaf(qrow[d], kb[lane * 65 + d], s);
            s *= SCALEf;
            const bool valid = (pos >= 0) && (pos >= tg - (WINn - 1)) && (pos <= tg);
            float sm = valid ? s : NEGf;
            float mnew = fmaxf(m[tl], warpMax(sm));
            float corr = expf(m[tl] - mnew);         // NEG-NEG -> exp(0)=1; l,o are 0 so safe
            float e = valid ? expf(sm - mnew) : 0.f;
            l[tl] = l[tl] * corr + warpSum(e);
            o0[tl] *= corr; o1[tl] *= corr;
            #pragma unroll
            for (int p = 0; p < 32; p++) {
                float ep = __shfl_sync(0xffffffffu, e, p);
                o0[tl] = fmaf(ep, vb[p * 64 + lane], o0[tl]);
                o1[tl] = fmaf(ep, vb[p * 64 + lane + 32], o1[tl]);
            }
            m[tl] = mnew;
        }
    }
    #pragma unroll
    for (int tl = 0; tl < TBw; tl++) {
        float inv = 1.f / l[tl];
        float* orow = g_owin + ((size_t)(t0 + tl) * Hn + g * HGn + w) * Dn;
        orow[lane] = o0[tl] * inv;
        orow[lane + 32] = o1[tl] * inv;
    }
}

// ---------------- gated combine -> 3-term split A operand ----------------
__global__ void combine_kernel() {
    int idx = blockIdx.x * blockDim.x + threadIdx.x;
    if (idx >= Tn * Hn * Dn) return;
    const int d = idx & 63;
    int rest = idx >> 6;
    const int h = rest % Hn;
    const int t = rest / Hn;
    const float* wrow = g_qkvw + (size_t)t * OUTDn + WOFF + h * 3;
    const float g0 = 1.f / (1.f + expf(-wrow[0]));
    const float g1 = 1.f / (1.f + expf(-wrow[1]));
    const float g2 = 1.f / (1.f + expf(-wrow[2]));
    float val = g0 * g_ocmp[idx] + g1 * g_osel[idx] + g2 * g_owin[idx];
    unsigned short hh, ll;
    f32_hl(val, hh, ll);
    unsigned short* p = (unsigned short*)g_a2o + (size_t)idx * 3;
    p[0] = hh; p[1] = hh; p[2] = ll;
}

// ---------------- launch ----------------
extern "C" void kernel_launch(void* const* d_in, const int* in_sizes, int n_in,
                              void* d_out, int out_size) {
    const float* x    = (const float*)d_in[0];
    const float* cosp = (const float*)d_in[1];
    const float* sinp = (const float*)d_in[2];
    const float* Wqkv = (const float*)d_in[3];
    const float* Wo   = (const float*)d_in[4];
    float* out = (float*)d_out;

    cudaFuncSetAttribute(gemm_mma_qkvw, cudaFuncAttributeMaxDynamicSharedMemorySize, GEMM_SMEM);
    cudaFuncSetAttribute(gemm_mma_out,  cudaFuncAttributeMaxDynamicSharedMemorySize, GEMM_SMEM);
    cudaFuncSetAttribute(win3_kernel,   cudaFuncAttributeMaxDynamicSharedMemorySize, WIN3_SMEM);

    conv_x_kernel<<<(Tn * HIDn + 255) / 256, 256>>>(x);
    {
        dim3 b(32, 32);
        tr_q_kernel<<<dim3(76, 64), b>>>(Wqkv);
        tr_o_kernel<<<dim3(64, 64), b>>>(Wo);
    }
    gemm_mma_qkvw<<<dim3(NPADn / 128, Tn / 128), 256, GEMM_SMEM>>>();
    rope_kernel<<<(Tn * (Hn + HKVn) * Dn + 255) / 256, 256>>>(cosp, sinp);
    pool_kernel<<<(NBn * Gn * Dn + 255) / 256, 256>>>();
    cmp2_kernel<<<dim3(Tn, Gn), 512>>>();
    topk_kernel<<<(Tn * Gn + 255) / 256, 256>>>();
    sel2_kernel<<<dim3(Tn, Gn), 512>>>();
    win3_kernel<<<dim3(Tn / TBw, Gn), 512, WIN3_SMEM>>>();
    combine_kernel<<<(Tn * Hn * Dn + 255) / 256, 256>>>();
    gemm_mma_out<<<dim3(HIDn / 128, Tn / 128), 256, GEMM_SMEM>>>(out);
}

// round 12
// speedup vs baseline: 1.0289x; 1.0289x over previous
#include <cuda_runtime.h>
#include <cuda_bf16.h>
#include <cstdint>
#include <math.h>

#define Tn    2048
#define HIDn  2048
#define Hn    32
#define HKVn  2
#define Dn    64
#define Gn    2
#define HGn   16
#define BLKn  32
#define NSELn 8
#define WINn  256
#define NBn   64
#define OUTDn 2400
#define NPADn 2432          /* 19*128 */
#define K2n   6144          /* 3x K=2048 : [ah,ah,al] x [bh,bl,bh] */
#define KOFF  (Hn*Dn)
#define VOFF  (KOFF + HKVn*Dn)
#define WOFF  (VOFF + HKVn*Dn)
#define NEGf  (-1e30f)
#define SCALEf 0.125f

// ---------------- scratch ----------------
__device__ float g_qkvw[Tn*OUTDn];
__device__ float g_q[Tn*Hn*Dn];
__device__ float g_k[Tn*HKVn*Dn];
__device__ float g_kcmp[NBn*Gn*Dn];
__device__ float g_vcmp[NBn*Gn*Dn];
__device__ float g_pcmp[Tn*Hn*NBn];
__device__ float g_ocmp[Tn*Hn*Dn];
__device__ float g_osel[Tn*Hn*Dn];
__device__ float g_owin[Tn*Hn*Dn];
__device__ int   g_selidx[Tn*Gn*NSELn];
__device__ __align__(16) __nv_bfloat16 g_a2x[(size_t)Tn*K2n];
__device__ __align__(16) __nv_bfloat16 g_a2o[(size_t)Tn*K2n];
__device__ __align__(16) __nv_bfloat16 g_b2q[(size_t)NPADn*K2n];
__device__ __align__(16) __nv_bfloat16 g_b2o[(size_t)HIDn*K2n];

// ---------------- helpers ----------------
__device__ __forceinline__ uint32_t smem_u32(const void* p) {
    uint32_t a;
    asm("{ .reg .u64 t; cvta.to.shared.u64 t, %1; cvt.u32.u64 %0, t; }" : "=r"(a) : "l"(p));
    return a;
}
#define CP_ASYNC16(dst, src) \
    asm volatile("cp.async.cg.shared.global [%0], [%1], 16;" :: "r"(dst), "l"(src) : "memory")
#define CP_COMMIT() asm volatile("cp.async.commit_group;" ::: "memory")
#define CP_WAIT1()  asm volatile("cp.async.wait_group 1;" ::: "memory")
#define CP_WAIT0()  asm volatile("cp.async.wait_group 0;" ::: "memory")

__device__ __forceinline__ void ldsm4(uint32_t &r0, uint32_t &r1, uint32_t &r2, uint32_t &r3,
                                      uint32_t addr) {
    asm volatile("ldmatrix.sync.aligned.m8n8.x4.shared.b16 {%0,%1,%2,%3}, [%4];"
                 : "=r"(r0), "=r"(r1), "=r"(r2), "=r"(r3) : "r"(addr));
}
__device__ __forceinline__ void mma_bf16(float* c, uint32_t a0, uint32_t a1, uint32_t a2,
                                         uint32_t a3, uint32_t b0, uint32_t b1) {
    asm volatile("mma.sync.aligned.m16n8k16.row.col.f32.bf16.bf16.f32 "
                 "{%0,%1,%2,%3}, {%4,%5,%6,%7}, {%8,%9}, {%0,%1,%2,%3};"
                 : "+f"(c[0]), "+f"(c[1]), "+f"(c[2]), "+f"(c[3])
                 : "r"(a0), "r"(a1), "r"(a2), "r"(a3), "r"(b0), "r"(b1));
}

__device__ __forceinline__ float warpMax(float v) {
    #pragma unroll
    for (int o = 16; o > 0; o >>= 1) v = fmaxf(v, __shfl_xor_sync(0xffffffffu, v, o));
    return v;
}
__device__ __forceinline__ float warpSum(float v) {
    #pragma unroll
    for (int o = 16; o > 0; o >>= 1) v += __shfl_xor_sync(0xffffffffu, v, o);
    return v;
}
__device__ __forceinline__ void f32_hl(float v, unsigned short &h, unsigned short &l) {
    __nv_bfloat16 bh = __float2bfloat16(v);
    float r = v - __bfloat162float(bh);
    __nv_bfloat16 bl = __float2bfloat16(r);
    h = __bfloat16_as_ushort(bh);
    l = __bfloat16_as_ushort(bl);
}

// ---------------- mma.sync split-bf16 GEMM body ----------------
// C[M,N] = A2[M,K2] @ B2[N,K2]^T ; 128x128 CTA tile, 512 threads (16 warps, 32x32 warp tile),
// K-chunk 32, 3-stage dynamic smem ring.
#define SAst 40                          /* smem row stride in bf16 elems (80 B) */
#define STAGE_BYTES (128*SAst*2)         /* 10240 per operand */
#define STAGE_PAIR  (2*STAGE_BYTES)      /* 20480 */
#define NSTAGE 3
#define GEMM_SMEM (NSTAGE*STAGE_PAIR)    /* 61440 */
__device__ __forceinline__ void gemm_body(const __nv_bfloat16* __restrict__ A2,
                                          const __nv_bfloat16* __restrict__ B2,
                                          float* __restrict__ C,
                                          int Nvalid, int ldc) {
    extern __shared__ __align__(16) unsigned char smem[];
    const uint32_t sbase = smem_u32(smem);
    const int tid = threadIdx.x;
    const int lane = tid & 31;
    const int warp = tid >> 5;          // 0..15
    const int wm = warp >> 2;           // 0..3  (32-row slice)
    const int wn = warp & 3;            // 0..3  (32-col slice)
    const int m0 = blockIdx.y * 128;
    const int n0 = blockIdx.x * 128;

    // global loads: 4 threads per row (8 bf16 = 16B each); 512 threads cover 128x32 exactly
    const int lrow = tid >> 2;          // 0..127
    const int lk   = (tid & 3) * 8;
    const __nv_bfloat16* aG = A2 + (size_t)(m0 + lrow) * K2n + lk;
    const __nv_bfloat16* bG = B2 + (size_t)(n0 + lrow) * K2n + lk;
    const uint32_t wOff = (uint32_t)(lrow * SAst + lk) * 2;

    float acc[2][4][4];
    #pragma unroll
    for (int i = 0; i < 2; i++)
        #pragma unroll
        for (int j = 0; j < 4; j++)
            #pragma unroll
            for (int r = 0; r < 4; r++) acc[i][j][r] = 0.f;

    const int NK = K2n / 32;   // 192

    const uint32_t aRow = (uint32_t)(wm * 32 + (lane & 15));
    const uint32_t aColSel = (uint32_t)((lane >> 4) * 8);
    const int ro = lane >> 3;
    const uint32_t bRow = (uint32_t)(wn * 32 + ((ro & 2) ? 8 : 0) + (lane & 7));
    const uint32_t bColSel = (uint32_t)((ro & 1) ? 8 : 0);

    #pragma unroll
    for (int s = 0; s < 2; s++) {
        uint32_t sA = sbase + (uint32_t)s * STAGE_PAIR;
        uint32_t sB = sA + STAGE_BYTES;
        CP_ASYNC16(sA + wOff, aG + (size_t)s * 32);
        CP_ASYNC16(sB + wOff, bG + (size_t)s * 32);
        CP_COMMIT();
    }

    for (int kc = 0; kc < NK; kc++) {
        if (kc + 2 < NK) CP_WAIT1(); else CP_WAIT0();
        __syncthreads();

        if (kc + 2 < NK) {
            uint32_t st = (uint32_t)((kc + 2) % 3) * STAGE_PAIR;
            uint32_t sA = sbase + st;
            uint32_t sB = sA + STAGE_BYTES;
            CP_ASYNC16(sA + wOff, aG + (size_t)(kc + 2) * 32);
            CP_ASYNC16(sB + wOff, bG + (size_t)(kc + 2) * 32);
            CP_COMMIT();
        }

        uint32_t st = (uint32_t)(kc % 3) * STAGE_PAIR;
        uint32_t sA = sbase + st;
        uint32_t sB = sA + STAGE_BYTES;

        #pragma unroll
        for (int s = 0; s < 2; s++) {
            uint32_t af[2][4];
            #pragma unroll
            for (int i = 0; i < 2; i++) {
                uint32_t addr = sA + ((aRow + i * 16) * SAst + s * 16 + aColSel) * 2;
                ldsm4(af[i][0], af[i][1], af[i][2], af[i][3], addr);
            }
            uint32_t bf[4][2];
            #pragma unroll
            for (int j2 = 0; j2 < 2; j2++) {
                uint32_t addr = sB + ((bRow + j2 * 16) * SAst + s * 16 + bColSel) * 2;
                uint32_t r0, r1, r2, r3;
                ldsm4(r0, r1, r2, r3, addr);
                bf[2*j2][0] = r0; bf[2*j2][1] = r1;
                bf[2*j2+1][0] = r2; bf[2*j2+1][1] = r3;
            }
            #pragma unroll
            for (int i = 0; i < 2; i++)
                #pragma unroll
                for (int j = 0; j < 4; j++)
                    mma_bf16(acc[i][j], af[i][0], af[i][1], af[i][2], af[i][3],
                             bf[j][0], bf[j][1]);
        }
    }

    const int rbase = m0 + wm * 32 + (lane >> 2);
    const int cbase = n0 + wn * 32 + (lane & 3) * 2;
    #pragma unroll
    for (int i = 0; i < 2; i++) {
        #pragma unroll
        for (int j = 0; j < 4; j++) {
            int rr = rbase + i * 16;
            int cc = cbase + j * 8;
            if (cc < Nvalid) {
                float* p0 = C + (size_t)rr * ldc + cc;
                p0[0] = acc[i][j][0];
                if (cc + 1 < Nvalid) p0[1] = acc[i][j][1];
                float* p1 = C + (size_t)(rr + 8) * ldc + cc;
                p1[0] = acc[i][j][2];
                if (cc + 1 < Nvalid) p1[1] = acc[i][j][3];
            }
        }
    }
}

__global__ __launch_bounds__(512) void gemm_mma_qkvw() {
    gemm_body(g_a2x, g_b2q, g_qkvw, OUTDn, OUTDn);
}
__global__ __launch_bounds__(512) void gemm_mma_out(float* __restrict__ C) {
    gemm_body(g_a2o, g_b2o, C, HIDn, HIDn);
}

// ---------------- conversions (3-term split: A=[h,h,l], B=[h,l,h]) ----------------
__global__ void conv_x_kernel(const float* __restrict__ x) {
    int idx = blockIdx.x * blockDim.x + threadIdx.x;
    if (idx >= Tn * HIDn) return;
    unsigned short h, l;
    f32_hl(x[idx], h, l);
    unsigned short* p = (unsigned short*)g_a2x + (size_t)idx * 3;
    p[0] = h; p[1] = h; p[2] = l;
}
__device__ __forceinline__ void tr_body(const float* __restrict__ W,
                                        __nv_bfloat16* __restrict__ B2,
                                        int Ncols, int Npad) {
    __shared__ float tile[32][33];
    int n = blockIdx.x * 32 + threadIdx.x;
    int k = blockIdx.y * 32 + threadIdx.y;
    tile[threadIdx.y][threadIdx.x] = (n < Ncols) ? W[(size_t)k * Ncols + n] : 0.f;
    __syncthreads();
    int nn = blockIdx.x * 32 + threadIdx.y;
    int kk = blockIdx.y * 32 + threadIdx.x;
    if (nn < Npad) {
        unsigned short h, l;
        f32_hl(tile[threadIdx.x][threadIdx.y], h, l);
        unsigned short* p = (unsigned short*)B2 + (size_t)nn * K2n + (size_t)kk * 3;
        p[0] = h; p[1] = l; p[2] = h;
    }
}
__global__ void tr_q_kernel(const float* __restrict__ W) { tr_body(W, g_b2q, OUTDn, NPADn); }
__global__ void tr_o_kernel(const float* __restrict__ W) { tr_body(W, g_b2o, HIDn, HIDn); }

// ---------------- RoPE ----------------
__global__ void rope_kernel(const float* __restrict__ cosp, const float* __restrict__ sinp) {
    int idx = blockIdx.x * blockDim.x + threadIdx.x;
    const int total = Tn * (Hn + HKVn) * Dn;
    if (idx >= total) return;
    const int d = idx & 63;
    int rest = idx >> 6;
    const int h = rest % (Hn + HKVn);
    const int t = rest / (Hn + HKVn);
    const float c = cosp[t * Dn + d];
    const float s = sinp[t * Dn + d];
    if (h < Hn) {
        const float* row = g_qkvw + (size_t)t * OUTDn + h * Dn;
        float x = row[d];
        float rot = (d < 32) ? -row[d + 32] : row[d - 32];
        g_q[((size_t)t * Hn + h) * Dn + d] = x * c + rot * s;
    } else {
        const int g = h - Hn;
        const float* row = g_qkvw + (size_t)t * OUTDn + KOFF + g * Dn;
        float x = row[d];
        float rot = (d < 32) ? -row[d + 32] : row[d - 32];
        g_k[((size_t)t * HKVn + g) * Dn + d] = x * c + rot * s;
    }
}

// ---------------- mean-pool ----------------
__global__ void pool_kernel() {
    int idx = blockIdx.x * blockDim.x + threadIdx.x;
    if (idx >= NBn * Gn * Dn) return;
    const int d = idx & 63;
    int rest = idx >> 6;
    const int g = rest % Gn;
    const int n = rest / Gn;
    float sk = 0.f, sv = 0.f;
    #pragma unroll 4
    for (int b = 0; b < BLKn; b++) {
        const int t = n * BLKn + b;
        sk += g_k[((size_t)t * HKVn + g) * Dn + d];
        sv += g_qkvw[(size_t)t * OUTDn + VOFF + g * Dn + d];
    }
    g_kcmp[idx] = sk * (1.f / BLKn);
    g_vcmp[idx] = sv * (1.f / BLKn);
}

// ---------------- compressed attention: CTA per (t,g), warp per head ----------------
__global__ __launch_bounds__(512) void cmp2_kernel() {
    const int t = blockIdx.x, g = blockIdx.y;
    const int tid = threadIdx.x, w = tid >> 5, lane = tid & 31;
    __shared__ float kc[NBn][65], vc[NBn][65], qs[HGn][Dn], ps[HGn][NBn];

    for (int i = tid; i < NBn * Dn; i += 512) {
        int n = i >> 6, d = i & 63;
        kc[n][d] = g_kcmp[((size_t)n * Gn + g) * Dn + d];
        vc[n][d] = g_vcmp[((size_t)n * Gn + g) * Dn + d];
    }
    for (int i = tid; i < HGn * Dn; i += 512) {
        int hg = i >> 6, d = i & 63;
        qs[hg][d] = g_q[((size_t)t * Hn + g * HGn + hg) * Dn + d];
    }
    __syncthreads();

    const int nvis = (t + 1) >> 5;
    float sc[2];
    #pragma unroll
    for (int ii = 0; ii < 2; ii++) {
        const int n = lane + ii * 32;
        float s = NEGf;
        if (n < nvis) {
            float acc = 0.f;
            #pragma unroll
            for (int d = 0; d < Dn; d++) acc = fmaf(qs[w][d], kc[n][d], acc);
            s = acc * SCALEf;
        }
        sc[ii] = s;
    }
    float p0 = 0.f, p1 = 0.f;
    if (nvis > 0) {
        float m = warpMax(fmaxf(sc[0], sc[1]));
        float e0 = expf(sc[0] - m), e1 = expf(sc[1] - m);
        float inv = 1.f / warpSum(e0 + e1);
        p0 = e0 * inv; p1 = e1 * inv;
    }
    ps[w][lane] = p0; ps[w][lane + 32] = p1;
    float* pout = g_pcmp + ((size_t)t * Hn + g * HGn + w) * NBn;
    pout[lane] = p0; pout[lane + 32] = p1;
    __syncwarp();

    float a0 = 0.f, a1 = 0.f;
    for (int n = 0; n < nvis; n++) {
        const float p = ps[w][n];
        a0 = fmaf(p, vc[n][lane], a0);
        a1 = fmaf(p, vc[n][lane + 32], a1);
    }
    float* orow = g_ocmp + ((size_t)t * Hn + g * HGn + w) * Dn;
    orow[lane] = a0; orow[lane + 32] = a1;
}

// ---------------- top-8 ----------------
__global__ void topk_kernel() {
    int idx = blockIdx.x * blockDim.x + threadIdx.x;
    if (idx >= Tn * Gn) return;
    const int g = idx % Gn, t = idx / Gn, tb = t >> 5;
    float imp[NBn];
    for (int n = 0; n < NBn; n++) {
        if (n > tb) { imp[n] = NEGf; continue; }
        float s = 0.f;
        #pragma unroll
        for (int hg = 0; hg < HGn; hg++)
            s += g_pcmp[((size_t)t * Hn + g * HGn + hg) * NBn + n];
        if (n == 0)  s += 1e4f;
        if (n == tb) s += 1e4f;
        imp[n] = s;
    }
    int* sel = g_selidx + ((size_t)t * Gn + g) * NSELn;
    for (int i = 0; i < NSELn; i++) {
        int best = 0; float bv = imp[0];
        for (int n = 1; n < NBn; n++)
            if (imp[n] > bv) { bv = imp[n]; best = n; }
        sel[i] = best;
        imp[best] = -2e30f;
    }
}

// ---------------- selection attention: CTA per (t,g) ----------------
__global__ __launch_bounds__(512) void sel2_kernel() {
    const int t = blockIdx.x, g = blockIdx.y;
    const int tid = threadIdx.x, w = tid >> 5, lane = tid & 31;
    __shared__ float kb[BLKn][65], qs[HGn][Dn], ps[HGn][NSELn * BLKn];
    __shared__ int sel[NSELn];

    for (int i = tid; i < HGn * Dn; i += 512) {
        int hg = i >> 6, d = i & 63;
        qs[hg][d] = g_q[((size_t)t * Hn + g * HGn + hg) * Dn + d];
    }
    if (tid < NSELn) sel[tid] = g_selidx[((size_t)t * Gn + g) * NSELn + tid];
    __syncthreads();

    float sc[NSELn];
    for (int i = 0; i < NSELn; i++) {
        const int base = sel[i] * BLKn;
        for (int j = tid; j < BLKn * Dn; j += 512) {
            int b = j >> 6, d = j & 63;
            kb[b][d] = g_k[((size_t)(base + b) * HKVn + g) * Dn + d];
        }
        __syncthreads();
        const int pos = base + lane;
        float s = NEGf;
        if (pos <= t) {
            float acc = 0.f;
            #pragma unroll
            for (int d = 0; d < Dn; d++) acc = fmaf(qs[w][d], kb[lane][d], acc);
            s = acc * SCALEf;
        }
        sc[i] = s;
        __syncthreads();
    }
    float lm = sc[0];
    #pragma unroll
    for (int i = 1; i < NSELn; i++) lm = fmaxf(lm, sc[i]);
    float m = warpMax(lm);
    float lsum = 0.f, ev[NSELn];
    #pragma unroll
    for (int i = 0; i < NSELn; i++) { ev[i] = expf(sc[i] - m); lsum += ev[i]; }
    float inv = 1.f / warpSum(lsum);
    #pragma unroll
    for (int i = 0; i < NSELn; i++) ps[w][i * 32 + lane] = ev[i] * inv;
    __syncwarp();

    float a0 = 0.f, a1 = 0.f;
    for (int i = 0; i < NSELn; i++) {
        const int base = sel[i] * BLKn;
        for (int j = tid; j < BLKn * Dn; j += 512) {
            int b = j >> 6, d = j & 63;
            kb[b][d] = g_qkvw[(size_t)(base + b) * OUTDn + VOFF + g * Dn + d];
        }
        __syncthreads();
        if (base <= t) {
            for (int b = 0; b < BLKn; b++) {
                const float p = ps[w][i * 32 + b];
                a0 = fmaf(p, kb[b][lane], a0);
                a1 = fmaf(p, kb[b][lane + 32], a1);
            }
        }
        __syncthreads();
    }
    float* orow = g_osel + ((size_t)t * Hn + g * HGn + w) * Dn;
    orow[lane] = a0; orow[lane + 32] = a1;
}

// ---------------- sliding window: CTA per (t,g) ----------------
__global__ __launch_bounds__(512) void win2_kernel() {
    const int t = blockIdx.x, g = blockIdx.y;
    const int tid = threadIdx.x, w = tid >> 5, lane = tid & 31;
    __shared__ float kb[BLKn][65], qs[HGn][Dn], ps[HGn][WINn];

    for (int i = tid; i < HGn * Dn; i += 512) {
        int hg = i >> 6, d = i & 63;
        qs[hg][d] = g_q[((size_t)t * Hn + g * HGn + hg) * Dn + d];
    }
    __syncthreads();

    const int p0 = t - (WINn - 1);
    float sc[8];
    for (int i = 0; i < 8; i++) {
        const int base = p0 + i * 32;
        for (int j = tid; j < BLKn * Dn; j += 512) {
            int b = j >> 6, d = j & 63;
            int row = base + b; if (row < 0) row = 0;
            kb[b][d] = g_k[((size_t)row * HKVn + g) * Dn + d];
        }
        __syncthreads();
        const int pos = base + lane;
        float s = NEGf;
        if (pos >= 0) {
            float acc = 0.f;
            #pragma unroll
            for (int d = 0; d < Dn; d++) acc = fmaf(qs[w][d], kb[lane][d], acc);
            s = acc * SCALEf;
        }
        sc[i] = s;
        __syncthreads();
    }
    float lm = sc[0];
    #pragma unroll
    for (int i = 1; i < 8; i++) lm = fmaxf(lm, sc[i]);
    float m = warpMax(lm);
    float lsum = 0.f, ev[8];
    #pragma unroll
    for (int i = 0; i < 8; i++) { ev[i] = expf(sc[i] - m); lsum += ev[i]; }
    float inv = 1.f / warpSum(lsum);
    #pragma unroll
    for (int i = 0; i < 8; i++) ps[w][i * 32 + lane] = ev[i] * inv;
    __syncwarp();

    float a0 = 0.f, a1 = 0.f;
    for (int i = 0; i < 8; i++) {
        const int base = p0 + i * 32;
        for (int j = tid; j < BLKn * Dn; j += 512) {
            int b = j >> 6, d = j & 63;
            int row = base + b; if (row < 0) row = 0;
            kb[b][d] = g_qkvw[(size_t)row * OUTDn + VOFF + g * Dn + d];
        }
        __syncthreads();
        for (int b = 0; b < BLKn; b++) {
            const float p = ps[w][i * 32 + b];
            a0 = fmaf(p, kb[b][lane], a0);
            a1 = fmaf(p, kb[b][lane + 32], a1);
        }
        __syncthreads();
    }
    float* orow = g_owin + ((size_t)t * Hn + g * HGn + w) * Dn;
    orow[lane] = a0; orow[lane + 32] = a1;
}

// ---------------- gated combine -> 3-term split A operand ----------------
__global__ void combine_kernel() {
    int idx = blockIdx.x * blockDim.x + threadIdx.x;
    if (idx >= Tn * Hn * Dn) return;
    const int d = idx & 63;
    int rest = idx >> 6;
    const int h = rest % Hn;
    const int t = rest / Hn;
    const float* wrow = g_qkvw + (size_t)t * OUTDn + WOFF + h * 3;
    const float g0 = 1.f / (1.f + expf(-wrow[0]));
    const float g1 = 1.f / (1.f + expf(-wrow[1]));
    const float g2 = 1.f / (1.f + expf(-wrow[2]));
    float val = g0 * g_ocmp[idx] + g1 * g_osel[idx] + g2 * g_owin[idx];
    unsigned short hh, ll;
    f32_hl(val, hh, ll);
    unsigned short* p = (unsigned short*)g_a2o + (size_t)idx * 3;
    p[0] = hh; p[1] = hh; p[2] = ll;
}

// ---------------- launch ----------------
extern "C" void kernel_launch(void* const* d_in, const int* in_sizes, int n_in,
                              void* d_out, int out_size) {
    const float* x    = (const float*)d_in[0];
    const float* cosp = (const float*)d_in[1];
    const float* sinp = (const float*)d_in[2];
    const float* Wqkv = (const float*)d_in[3];
    const float* Wo   = (const float*)d_in[4];
    float* out = (float*)d_out;

    cudaFuncSetAttribute(gemm_mma_qkvw, cudaFuncAttributeMaxDynamicSharedMemorySize, GEMM_SMEM);
    cudaFuncSetAttribute(gemm_mma_out,  cudaFuncAttributeMaxDynamicSharedMemorySize, GEMM_SMEM);

    conv_x_kernel<<<(Tn * HIDn + 255) / 256, 256>>>(x);
    {
        dim3 b(32, 32);
        tr_q_kernel<<<dim3(76, 64), b>>>(Wqkv);
        tr_o_kernel<<<dim3(64, 64), b>>>(Wo);
    }
    gemm_mma_qkvw<<<dim3(NPADn / 128, Tn / 128), 512, GEMM_SMEM>>>();
    rope_kernel<<<(Tn * (Hn + HKVn) * Dn + 255) / 256, 256>>>(cosp, sinp);
    pool_kernel<<<(NBn * Gn * Dn + 255) / 256, 256>>>();
    cmp2_kernel<<<dim3(Tn, Gn), 512>>>();
    topk_kernel<<<(Tn * Gn + 255) / 256, 256>>>();
    sel2_kernel<<<dim3(Tn, Gn), 512>>>();
    win2_kernel<<<dim3(Tn, Gn), 512>>>();
    combine_kernel<<<(Tn * Hn * Dn + 255) / 256, 256>>>();
    gemm_mma_out<<<dim3(HIDn / 128, Tn / 128), 512, GEMM_SMEM>>>(out);
}